// round 9
// baseline (speedup 1.0000x reference)
#include <cuda_runtime.h>
#include <math.h>

#define Bn 16
#define Cn 3
#define Hn 512
#define Wn 512
#define HW (Hn * Wn)           // 262144
#define CHW (Cn * HW)          // 786432
#define NTOT (Bn * Cn * HW)    // 12582912

#define TW 64                  // owned tile width
#define TH 32                  // owned tile height
#define HTW 68                 // smem width: idx k = global col (w0-1+k), k=0..67
#define HTH (TH + 2)           // 34
#define VPR 18                 // 18 gmem float4 vectors per halo row (cols w0-4..w0+67)
#define NITEMS (HTH * VPR)     // 612
#define NTHREADS 256

#define GX (Wn / TW)           // 8
#define GY (Hn / TH)           // 16
#define BPB (GX * GY)          // 128
#define NBLK (BPB * Bn)        // 2048

// Per-block float partials (RAW scale, deferred 1/255), written exactly once.
__device__ float g_part[3][NBLK];
__device__ unsigned int g_count;   // zero-init; last block resets to 0

__device__ __forceinline__ int reflect(int i, int n) {
    return (i < 0) ? -i : ((i >= n) ? 2 * n - 2 - i : i);
}
__device__ __forceinline__ float sgnsel(float rs, float re) {
    return (rs < re) ? __int_as_float(__float_as_int(rs) | 0x80000000u) : rs;
}

// Write 4 residuals to smem idx [4v-3 .. 4v], predicated to [0, HTW)
__device__ __forceinline__ void store4(float* __restrict__ rt, int ty, int v,
                                       float x, float y, float z, float w) {
    const int idx0 = 4 * v - 3;
    float* row = rt + ty * HTW;
    if (idx0     >= 0 && idx0     < HTW) row[idx0]     = x;
    if (idx0 + 1 >= 0 && idx0 + 1 < HTW) row[idx0 + 1] = y;
    if (idx0 + 2 >= 0 && idx0 + 2 < HTW) row[idx0 + 2] = z;
    if (idx0 + 3 < HTW)                  row[idx0 + 3] = w;   // idx0+3 >= 0 always
}

// Fast path: interior-x blocks, no w reflection needed for gmem.
__device__ __forceinline__ void tile_vec_fast(
    float* __restrict__ rt, int t, int w0, int h0, int base,
    const float* __restrict__ sr, const float* __restrict__ srema,
    const float* __restrict__ hr)
{
    const int ty = t / VPR;
    const int v  = t - ty * VPR;
    const int gh = reflect(h0 - 1 + ty, Hn);
    const int ix = base + gh * Wn + (w0 - 4 + 4 * v);

    float4 h0v = __ldg((const float4*)(hr    + ix));
    float4 s0v = __ldg((const float4*)(sr    + ix));
    float4 e0v = __ldg((const float4*)(srema + ix));
    float4 h1v = __ldg((const float4*)(hr    + ix + HW));
    float4 s1v = __ldg((const float4*)(sr    + ix + HW));
    float4 e1v = __ldg((const float4*)(srema + ix + HW));
    float4 h2v = __ldg((const float4*)(hr    + ix + 2 * HW));
    float4 s2v = __ldg((const float4*)(sr    + ix + 2 * HW));
    float4 e2v = __ldg((const float4*)(srema + ix + 2 * HW));

    float ox, oy, oz, ow;
    {
        float rs = fabsf(h0v.x - s0v.x) + fabsf(h1v.x - s1v.x) + fabsf(h2v.x - s2v.x);
        float re = fabsf(h0v.x - e0v.x) + fabsf(h1v.x - e1v.x) + fabsf(h2v.x - e2v.x);
        ox = sgnsel(rs, re);
    }
    {
        float rs = fabsf(h0v.y - s0v.y) + fabsf(h1v.y - s1v.y) + fabsf(h2v.y - s2v.y);
        float re = fabsf(h0v.y - e0v.y) + fabsf(h1v.y - e1v.y) + fabsf(h2v.y - e2v.y);
        oy = sgnsel(rs, re);
    }
    {
        float rs = fabsf(h0v.z - s0v.z) + fabsf(h1v.z - s1v.z) + fabsf(h2v.z - s2v.z);
        float re = fabsf(h0v.z - e0v.z) + fabsf(h1v.z - e1v.z) + fabsf(h2v.z - e2v.z);
        oz = sgnsel(rs, re);
    }
    {
        float rs = fabsf(h0v.w - s0v.w) + fabsf(h1v.w - s1v.w) + fabsf(h2v.w - s2v.w);
        float re = fabsf(h0v.w - e0v.w) + fabsf(h1v.w - e1v.w) + fabsf(h2v.w - e2v.w);
        ow = sgnsel(rs, re);
    }
    store4(rt, ty, v, ox, oy, oz, ow);
}

// General path: edge-x blocks with per-element reflection.
__device__ __forceinline__ void tile_vec_gen(
    float* __restrict__ rt, int t, int w0, int h0, int base,
    const float* __restrict__ sr, const float* __restrict__ srema,
    const float* __restrict__ hr)
{
    const int ty  = t / VPR;
    const int v   = t - ty * VPR;
    const int gh  = reflect(h0 - 1 + ty, Hn);
    const int gw0 = w0 - 4 + 4 * v;
    float vals[4];
#pragma unroll
    for (int e = 0; e < 4; ++e) {
        const int gw = reflect(gw0 + e, Wn);
        const int ix = base + gh * Wn + gw;
        float rs = 0.f, re = 0.f;
#pragma unroll
        for (int c = 0; c < Cn; ++c) {
            float h  = __ldg(hr    + ix + c * HW);
            float s  = __ldg(sr    + ix + c * HW);
            float se = __ldg(srema + ix + c * HW);
            rs += fabsf(h - s);
            re += fabsf(h - se);
        }
        vals[e] = sgnsel(rs, re);
    }
    store4(rt, ty, v, vals[0], vals[1], vals[2], vals[3]);
}

// Sliding-window row sums: 6 values -> 4 overlapping 3-sums (abs and square).
__device__ __forceinline__ void rowsums(float4 a, float4 b2, float* A, float* B) {
    float p0 = fabsf(a.x), p1 = fabsf(a.y), p2 = fabsf(a.z);
    float p3 = fabsf(a.w), p4 = fabsf(b2.x), p5 = fabsf(b2.y);
    float q0 = p0 * p0, q1 = p1 * p1, q2 = p2 * p2;
    float q3 = p3 * p3, q4 = p4 * p4, q5 = p5 * p5;
    A[0] = p0 + p1 + p2;  A[1] = p1 + p2 + p3;
    A[2] = p2 + p3 + p4;  A[3] = p3 + p4 + p5;
    B[0] = q0 + q1 + q2;  B[1] = q1 + q2 + q3;
    B[2] = q2 + q3 + q4;  B[3] = q3 + q4 + q5;
}

// ---------------------------------------------------------------------------
__global__ __launch_bounds__(NTHREADS) void fused_kernel(
    const float* __restrict__ sr,
    const float* __restrict__ srema,
    const float* __restrict__ hr,
    float* __restrict__ out)
{
    __shared__ float rt[HTH * HTW];   // signed raw residuals; idx k = col w0-1+k

    const int tid = threadIdx.x;
    const int w0  = blockIdx.x * TW;
    const int h0  = blockIdx.y * TH;
    const int b   = blockIdx.z;
    const int base = b * CHW;

    // --- Phase 1 --------------------------------------------------------------
    if (blockIdx.x > 0 && blockIdx.x < GX - 1) {
        tile_vec_fast(rt, tid,       w0, h0, base, sr, srema, hr);
        tile_vec_fast(rt, tid + 256, w0, h0, base, sr, srema, hr);
        if (tid < NITEMS - 512)
            tile_vec_fast(rt, tid + 512, w0, h0, base, sr, srema, hr);
    } else {
        tile_vec_gen(rt, tid,       w0, h0, base, sr, srema, hr);
        tile_vec_gen(rt, tid + 256, w0, h0, base, sr, srema, hr);
        if (tid < NITEMS - 512)
            tile_vec_gen(rt, tid + 512, w0, h0, base, sr, srema, hr);
    }
    __syncthreads();

    // --- Phase 2: 4-pixel groups, 6 LDS.128 per group --------------------------
    // Group g: owned row r = g>>4, cols c0..c0+3 (c0 = (g&15)*4).
    // Window cols for the group = smem idx c0..c0+5 (idx = col - (w0-1) maps
    // owned col c to idx c+1; window left = idx c0). Two aligned float4s cover it.
    float lsum = 0.f, lsq = 0.f, lS = 0.f;
#pragma unroll
    for (int k = 0; k < 2; ++k) {
        const int g  = tid + k * NTHREADS;
        const int r  = g >> 4;
        const int c0 = (g & 15) << 2;
        const float* bp = rt + r * HTW + c0;

        float4 t0a = *(const float4*)(bp);
        float4 t0b = *(const float4*)(bp + 4);
        float4 t1a = *(const float4*)(bp + HTW);
        float4 t1b = *(const float4*)(bp + HTW + 4);
        float4 t2a = *(const float4*)(bp + 2 * HTW);
        float4 t2b = *(const float4*)(bp + 2 * HTW + 4);

        float A0[4], B0[4], A1[4], B1[4], A2[4], B2[4];
        rowsums(t0a, t0b, A0, B0);
        rowsums(t1a, t1b, A1, B1);
        rowsums(t2a, t2b, A2, B2);

        const float cen[4] = { t1a.y, t1a.z, t1a.w, t1b.x };  // signed centers
#pragma unroll
        for (int x = 0; x < 4; ++x) {
            float s  = A0[x] + A1[x] + A2[x];
            float sq = B0[x] + B1[x] + B2[x];
            float lv = (sq - s * s * (1.0f / 9.0f)) * (1.0f / 8.0f);
            float r4 = fabsf(cen[x]);
            lS   += signbit(cen[x]) ? 0.0f : fabsf(lv) * r4;
            lsum += r4;
            lsq  += r4 * r4;
        }
    }

    // --- Block reduction --------------------------------------------------------
    __shared__ float wsum[8], wsq[8], wS[8];
#pragma unroll
    for (int o = 16; o > 0; o >>= 1) {
        lsum += __shfl_down_sync(0xffffffffu, lsum, o);
        lsq  += __shfl_down_sync(0xffffffffu, lsq,  o);
        lS   += __shfl_down_sync(0xffffffffu, lS,   o);
    }
    const int warp = tid >> 5;
    if ((tid & 31) == 0) { wsum[warp] = lsum; wsq[warp] = lsq; wS[warp] = lS; }
    __syncthreads();

    __shared__ bool isLast;
    if (tid == 0) {
        float a = 0.f, cc = 0.f, d = 0.f;
#pragma unroll
        for (int i = 0; i < 8; ++i) { a += wsum[i]; cc += wsq[i]; d += wS[i]; }
        const int bid = blockIdx.x + GX * blockIdx.y + BPB * blockIdx.z;
        g_part[0][bid] = a;
        g_part[1][bid] = cc;
        g_part[2][bid] = d;
        __threadfence();
        unsigned prev = atomicAdd(&g_count, 1u);
        isLast = (prev == NBLK - 1);
    }
    __syncthreads();

    // --- Last block: per-batch patch weight + final loss -------------------------
    if (isLast) {
        if (tid == 0) g_count = 0;   // reset for next graph replay
        __shared__ float sres[Bn];
        const int warp2 = tid >> 5;
        const int lane  = tid & 31;
#pragma unroll
        for (int j = 0; j < 2; ++j) {
            const int bb  = warp2 * 2 + j;
            const int idx = bb * BPB + lane * 4;
            float s = 0.f, sq = 0.f, S = 0.f;
#pragma unroll
            for (int e = 0; e < 4; ++e) {
                s  += __ldcg(&g_part[0][idx + e]);
                sq += __ldcg(&g_part[1][idx + e]);
                S  += __ldcg(&g_part[2][idx + e]);
            }
#pragma unroll
            for (int o = 16; o > 0; o >>= 1) {
                s  += __shfl_down_sync(0xffffffffu, s,  o);
                sq += __shfl_down_sync(0xffffffffu, sq, o);
                S  += __shfl_down_sync(0xffffffffu, S,  o);
            }
            if (lane == 0) {
                const float n = (float)HW;
                float var = (sq - s * s / n) / (n - 1.0f);
                float w = (var > 0.0f) ? exp2f(0.2f * log2f(var)) : 0.0f;
                sres[bb] = w * S;
            }
        }
        __syncthreads();
        if (tid == 0) {
            float acc = 0.f;
#pragma unroll
            for (int i = 0; i < Bn; ++i) acc += sres[i];
            // loss = 255^(-2.4)/NTOT * sum_b var_raw^0.2 * S_raw
            double Kd = pow(255.0, -2.4) / (double)NTOT;
            out[0] = (float)((double)acc * Kd);
        }
    }
}

// ---------------------------------------------------------------------------
extern "C" void kernel_launch(void* const* d_in, const int* in_sizes, int n_in,
                              void* d_out, int out_size) {
    const float* sr    = (const float*)d_in[0];
    const float* srema = (const float*)d_in[1];
    const float* hr    = (const float*)d_in[2];
    float* out = (float*)d_out;

    dim3 blk(NTHREADS, 1, 1);
    dim3 grd(GX, GY, Bn);
    fused_kernel<<<grd, blk>>>(sr, srema, hr, out);
}